// round 7
// baseline (speedup 1.0000x reference)
#include <cuda_runtime.h>

#define NN 100000
#define NE 1600000
#define DIM 128
#define DV (DIM/4)   // 32 float4 per row

// multi-block scan geometry: 256 threads x 8 elems = 2048 elems per block
#define SCAN_PER 2048
#define NBLK ((NN + SCAN_PER - 1) / SCAN_PER)   // 49

// smem row pitch (32-bit words): 128 + 8 pad -> W-frag loads conflict-free
#define PITCH 136

// ---- device scratch (allocations forbidden; globals are the sanctioned path) ----
__device__ int   g_deg_in [NN];
__device__ int   g_deg_out[NN];
__device__ float g_ns[NN];           // rsqrt(out-degree incl self-loop)
__device__ float g_nd[NN];           // rsqrt(in-degree  incl self-loop)
__device__ int   g_off[NN + 1];      // CSR offsets by dst
__device__ int   g_cur[NN];
__device__ int   g_esrc[NE];         // src ids bucketed by dst
__device__ int   g_bsum [NBLK];
__device__ int   g_bbase[NBLK];
__device__ float g_A[NN * DIM];      // ping feature buffer (holds h * norm_src)
__device__ float g_B[NN * DIM];      // pong feature buffer

// ---------------- preprocessing ----------------

__global__ void k_zero() {
    int i = blockIdx.x * blockDim.x + threadIdx.x;
    if (i < NN) { g_deg_in[i] = 0; g_deg_out[i] = 0; }
}

__global__ void k_count(const int* __restrict__ src, const int* __restrict__ dst) {
    int e = blockIdx.x * blockDim.x + threadIdx.x;
    if (e < NE) {
        atomicAdd(&g_deg_out[src[e]], 1);
        atomicAdd(&g_deg_in [dst[e]], 1);
    }
}

__global__ void k_norm() {
    int i = blockIdx.x * blockDim.x + threadIdx.x;
    if (i < NN) {
        g_ns[i] = rsqrtf((float)(g_deg_out[i] + 1));   // +1: self-loop
        g_nd[i] = rsqrtf((float)(g_deg_in [i] + 1));
    }
}

__global__ void k_bsum() {
    __shared__ int wsum[8];
    int tid = threadIdx.x, lane = tid & 31, wid = tid >> 5;
    int base = blockIdx.x * SCAN_PER + tid * 8;
    int t = 0;
    #pragma unroll
    for (int j = 0; j < 8; j++) {
        int i = base + j;
        t += (i < NN) ? g_deg_in[i] : 0;
    }
    #pragma unroll
    for (int o = 16; o > 0; o >>= 1) t += __shfl_down_sync(0xffffffffu, t, o);
    if (lane == 0) wsum[wid] = t;
    __syncthreads();
    if (tid == 0) {
        int s = 0;
        #pragma unroll
        for (int w = 0; w < 8; w++) s += wsum[w];
        g_bsum[blockIdx.x] = s;
    }
}

__global__ void k_bscan() {
    __shared__ int sm[64];
    int tid = threadIdx.x;                       // 64 threads
    sm[tid] = (tid < NBLK) ? g_bsum[tid] : 0;
    __syncthreads();
    #pragma unroll
    for (int o = 1; o < 64; o <<= 1) {
        int v = (tid >= o) ? sm[tid - o] : 0;
        __syncthreads();
        sm[tid] += v;
        __syncthreads();
    }
    if (tid < NBLK) g_bbase[tid] = (tid > 0) ? sm[tid - 1] : 0;
    if (tid == 0) g_off[NN] = NE;
}

__global__ void k_lscan() {
    __shared__ int wsum[8];
    int tid = threadIdx.x, lane = tid & 31, wid = tid >> 5;
    int base = blockIdx.x * SCAN_PER + tid * 8;

    int v[8], t = 0;
    #pragma unroll
    for (int j = 0; j < 8; j++) {
        int i = base + j;
        v[j] = (i < NN) ? g_deg_in[i] : 0;
        t += v[j];
    }
    int x = t;
    #pragma unroll
    for (int o = 1; o < 32; o <<= 1) {
        int y = __shfl_up_sync(0xffffffffu, x, o);
        if (lane >= o) x += y;
    }
    if (lane == 31) wsum[wid] = x;
    int lane_excl = x - t;
    __syncthreads();
    if (tid == 0) {
        int s = 0;
        #pragma unroll
        for (int w = 0; w < 8; w++) { int a = wsum[w]; wsum[w] = s; s += a; }
    }
    __syncthreads();
    int run = g_bbase[blockIdx.x] + wsum[wid] + lane_excl;
    #pragma unroll
    for (int j = 0; j < 8; j++) {
        int i = base + j;
        if (i < NN) { g_off[i] = run; g_cur[i] = run; }
        run += v[j];
    }
}

__global__ void k_fill(const int* __restrict__ src, const int* __restrict__ dst) {
    int e = blockIdx.x * blockDim.x + threadIdx.x;
    if (e < NE) {
        int p = atomicAdd(&g_cur[dst[e]], 1);
        g_esrc[p] = src[e];
    }
}

// layer-0 input scaling: g_A = inputs * norm_src
__global__ void k_scale0(const float* __restrict__ in) {
    int i = blockIdx.x * blockDim.x + threadIdx.x;
    if (i >= NN * DV) return;
    float s = g_ns[i / DV];
    float4 v = ((const float4*)in)[i];
    v.x *= s; v.y *= s; v.z *= s; v.w *= s;
    ((float4*)g_A)[i] = v;
}

// ---------------- fused layer kernel ----------------
// Per block: 128 output rows.
//  phase 1: stage W (tf32) ; gather-aggregate this block's 128 nodes from the
//           ping buffer (self-loop + in-edges, fp32), scale by norm_dst,
//           convert tf32, write into A smem tile.
//  phase 2: 128x128 tf32 mma.sync (16 warps, 32x32 warp tiles).
//  epilogue: + bias; if fuse: relu * norm_src -> pong buffer, else -> out_ext.
// Ping-pong avoids the same-buffer RAW hazard across concurrent blocks.

__device__ __forceinline__ unsigned f2tf32(float x) {
    unsigned u;
    asm("cvt.rna.tf32.f32 %0, %1;" : "=r"(u) : "f"(x));
    return u;
}

__global__ void __launch_bounds__(512, 1)
k_layer(const float* __restrict__ W, const float* __restrict__ bias,
        float* __restrict__ out_ext, int which_in, int fuse) {
    extern __shared__ unsigned sm[];
    unsigned* Asm = sm;                 // 128 x PITCH (tf32 bits)
    unsigned* Wsm = sm + DIM * PITCH;   // 128 x PITCH (tf32 bits), [k][n]

    int tid  = threadIdx.x;
    int lane = tid & 31, w = tid >> 5;  // 16 warps
    int row0 = blockIdx.x * 128;

    const float4* __restrict__ in4 = which_in ? (const float4*)g_B
                                              : (const float4*)g_A;

    // stage W[k][n] -> tf32 (8 iters of 512 threads)
    const float4* W4 = (const float4*)W;
    for (int i = tid; i < DIM * DV; i += 512) {
        int r = i >> 5, c4 = i & 31;
        float4 v = W4[i];
        *(uint4*)&Wsm[r * PITCH + c4 * 4] =
            make_uint4(f2tf32(v.x), f2tf32(v.y), f2tf32(v.z), f2tf32(v.w));
    }

    // gather-aggregate: warp w handles rows row0 + w*8 .. +7
    #pragma unroll 1
    for (int i = 0; i < 8; i++) {
        int rloc = w * 8 + i;
        int row  = row0 + rloc;
        uint4 u = make_uint4(0u, 0u, 0u, 0u);
        if (row < NN) {
            float4 a = in4[row * DV + lane];           // self-loop
            float ax = a.x, ay = a.y, az = a.z, aw = a.w;
            int beg = __ldg(&g_off[row]), end = __ldg(&g_off[row + 1]);
            for (int base = beg; base < end; base += 32) {
                int cnt = min(32, end - base);
                int e = (lane < cnt) ? __ldg(&g_esrc[base + lane]) : 0;
                #pragma unroll 8
                for (int j = 0; j < cnt; j++) {
                    int s = __shfl_sync(0xffffffffu, e, j);
                    float4 v = __ldg(&in4[s * DV + lane]);
                    ax += v.x; ay += v.y; az += v.z; aw += v.w;
                }
            }
            float s = g_nd[row];
            u = make_uint4(f2tf32(ax * s), f2tf32(ay * s),
                           f2tf32(az * s), f2tf32(aw * s));
        }
        *(uint4*)&Asm[rloc * PITCH + lane * 4] = u;
    }
    __syncthreads();

    // mma phase: 16 warps = 4m x 4n grid of 32x32 warp tiles
    int g = lane >> 2, t = lane & 3;
    int m0w = (w & 3) * 32;
    int n0w = (w >> 2) * 32;

    float acc[2][4][4];
    #pragma unroll
    for (int mt = 0; mt < 2; mt++)
        #pragma unroll
        for (int nt = 0; nt < 4; nt++)
            #pragma unroll
            for (int j = 0; j < 4; j++) acc[mt][nt][j] = 0.f;

    #pragma unroll 4
    for (int k0 = 0; k0 < DIM; k0 += 8) {
        unsigned a[2][4], b[4][2];
        #pragma unroll
        for (int mt = 0; mt < 2; mt++) {
            int r = m0w + mt * 16 + g;
            a[mt][0] = Asm[r * PITCH + k0 + t];
            a[mt][1] = Asm[(r + 8) * PITCH + k0 + t];
            a[mt][2] = Asm[r * PITCH + k0 + t + 4];
            a[mt][3] = Asm[(r + 8) * PITCH + k0 + t + 4];
        }
        #pragma unroll
        for (int nt = 0; nt < 4; nt++) {
            int c = n0w + nt * 8 + g;
            b[nt][0] = Wsm[(k0 + t) * PITCH + c];
            b[nt][1] = Wsm[(k0 + t + 4) * PITCH + c];
        }
        #pragma unroll
        for (int mt = 0; mt < 2; mt++)
            #pragma unroll
            for (int nt = 0; nt < 4; nt++) {
                asm volatile(
                    "mma.sync.aligned.m16n8k8.row.col.f32.tf32.tf32.f32 "
                    "{%0,%1,%2,%3}, {%4,%5,%6,%7}, {%8,%9}, {%0,%1,%2,%3};"
                    : "+f"(acc[mt][nt][0]), "+f"(acc[mt][nt][1]),
                      "+f"(acc[mt][nt][2]), "+f"(acc[mt][nt][3])
                    : "r"(a[mt][0]), "r"(a[mt][1]), "r"(a[mt][2]), "r"(a[mt][3]),
                      "r"(b[nt][0]), "r"(b[nt][1]));
            }
    }

    // epilogue
    float* O = fuse ? (which_in ? g_A : g_B) : out_ext;
    #pragma unroll
    for (int mt = 0; mt < 2; mt++) {
        int rl = row0 + m0w + mt * 16 + g;
        int rh = rl + 8;
        float sl = 1.f, sh = 1.f;
        if (fuse) {
            if (rl < NN) sl = g_ns[rl];
            if (rh < NN) sh = g_ns[rh];
        }
        #pragma unroll
        for (int nt = 0; nt < 4; nt++) {
            int c = n0w + nt * 8 + 2 * t;
            float2 bb = *(const float2*)&bias[c];
            if (rl < NN) {
                float2 o;
                o.x = acc[mt][nt][0] + bb.x;
                o.y = acc[mt][nt][1] + bb.y;
                if (fuse) { o.x = fmaxf(o.x, 0.f) * sl; o.y = fmaxf(o.y, 0.f) * sl; }
                *(float2*)&O[rl * DIM + c] = o;
            }
            if (rh < NN) {
                float2 o;
                o.x = acc[mt][nt][2] + bb.x;
                o.y = acc[mt][nt][3] + bb.y;
                if (fuse) { o.x = fmaxf(o.x, 0.f) * sh; o.y = fmaxf(o.y, 0.f) * sh; }
                *(float2*)&O[rh * DIM + c] = o;
            }
        }
    }
}

// ---------------- launch ----------------

extern "C" void kernel_launch(void* const* d_in, const int* in_sizes, int n_in,
                              void* d_out, int out_size) {
    const float* inp = (const float*)d_in[0];   // [NN, DIM]
    const float* Ws  = (const float*)d_in[1];   // [3, DIM, DIM]
    const float* bs  = (const float*)d_in[2];   // [3, DIM]
    const int*   src = (const int*)  d_in[3];   // [NE]
    const int*   dst = (const int*)  d_in[4];   // [NE]
    float* out = (float*)d_out;                 // [NN, DIM]

    const int LAYER_SMEM = 2 * DIM * PITCH * (int)sizeof(unsigned);  // 139264 B
    cudaFuncSetAttribute(k_layer, cudaFuncAttributeMaxDynamicSharedMemorySize,
                         LAYER_SMEM);

    int nb_n = (NN + 255) / 256;
    int nb_e = (NE + 255) / 256;

    // preprocessing: degrees, norms, CSR by dst (multi-block scan)
    k_zero <<<nb_n, 256>>>();
    k_count<<<nb_e, 256>>>(src, dst);
    k_norm <<<nb_n, 256>>>();
    k_bsum <<<NBLK, 256>>>();
    k_bscan<<<1, 64>>>();
    k_lscan<<<NBLK, 256>>>();
    k_fill <<<nb_e, 256>>>(src, dst);

    // layer 0 input scaling: g_A = inputs * norm_src
    k_scale0<<<(NN * DV + 255) / 256, 256>>>(inp);

    int nb_layer = (NN + 127) / 128;   // 782

    // ping-pong: L0 reads g_A -> g_B; L1 reads g_B -> g_A; L2 reads g_A -> out
    k_layer<<<nb_layer, 512, LAYER_SMEM>>>(Ws + 0 * DIM * DIM, bs + 0 * DIM,
                                           out, /*which_in=*/0, /*fuse=*/1);
    k_layer<<<nb_layer, 512, LAYER_SMEM>>>(Ws + 1 * DIM * DIM, bs + 1 * DIM,
                                           out, /*which_in=*/1, /*fuse=*/1);
    k_layer<<<nb_layer, 512, LAYER_SMEM>>>(Ws + 2 * DIM * DIM, bs + 2 * DIM,
                                           out, /*which_in=*/0, /*fuse=*/0);
}

// round 9
// speedup vs baseline: 1.7054x; 1.7054x over previous
#include <cuda_runtime.h>

#define NN 100000
#define NE 1600000
#define DIM 128
#define DV (DIM/4)   // 32 float4 per row

// multi-block scan geometry: 256 threads x 8 elems = 2048 elems per block
#define SCAN_PER 2048
#define NBLK ((NN + SCAN_PER - 1) / SCAN_PER)   // 49

// smem row pitch (32-bit words): 128 + 8 pad -> W-frag loads conflict-free
#define PITCH 136
#define NT ((NN + 127) / 128)     // 782 row tiles
#define GRID_P 148                // persistent gemm grid

// ---- device scratch (allocations forbidden; globals are the sanctioned path) ----
__device__ int      g_deg_in [NN];
__device__ int      g_deg_out[NN];
__device__ float    g_ns[NN];        // rsqrt(out-degree incl self-loop)
__device__ float    g_nd[NN];        // rsqrt(in-degree  incl self-loop)
__device__ int      g_off[NN + 1];   // CSR offsets by dst
__device__ int      g_cur[NN];
__device__ int      g_esrc[NE];      // src ids bucketed by dst
__device__ int      g_bsum [NBLK];
__device__ int      g_bbase[NBLK];
__device__ float    g_A[NN * DIM];   // fp32 feature buffer (h * norm_src)
__device__ unsigned g_T[NN * DIM];   // aggregated, *norm_dst, tf32 bits

// ---------------- preprocessing ----------------

__global__ void k_zero() {
    int i = blockIdx.x * blockDim.x + threadIdx.x;
    if (i < NN) { g_deg_in[i] = 0; g_deg_out[i] = 0; }
}

__global__ void k_count(const int* __restrict__ src, const int* __restrict__ dst) {
    int e = blockIdx.x * blockDim.x + threadIdx.x;
    if (e < NE) {
        atomicAdd(&g_deg_out[src[e]], 1);
        atomicAdd(&g_deg_in [dst[e]], 1);
    }
}

__global__ void k_norm() {
    int i = blockIdx.x * blockDim.x + threadIdx.x;
    if (i < NN) {
        g_ns[i] = rsqrtf((float)(g_deg_out[i] + 1));   // +1: self-loop
        g_nd[i] = rsqrtf((float)(g_deg_in [i] + 1));
    }
}

__global__ void k_bsum() {
    __shared__ int wsum[8];
    int tid = threadIdx.x, lane = tid & 31, wid = tid >> 5;
    int base = blockIdx.x * SCAN_PER + tid * 8;
    int t = 0;
    #pragma unroll
    for (int j = 0; j < 8; j++) {
        int i = base + j;
        t += (i < NN) ? g_deg_in[i] : 0;
    }
    #pragma unroll
    for (int o = 16; o > 0; o >>= 1) t += __shfl_down_sync(0xffffffffu, t, o);
    if (lane == 0) wsum[wid] = t;
    __syncthreads();
    if (tid == 0) {
        int s = 0;
        #pragma unroll
        for (int w = 0; w < 8; w++) s += wsum[w];
        g_bsum[blockIdx.x] = s;
    }
}

__global__ void k_bscan() {
    __shared__ int sm[64];
    int tid = threadIdx.x;                       // 64 threads
    sm[tid] = (tid < NBLK) ? g_bsum[tid] : 0;
    __syncthreads();
    #pragma unroll
    for (int o = 1; o < 64; o <<= 1) {
        int v = (tid >= o) ? sm[tid - o] : 0;
        __syncthreads();
        sm[tid] += v;
        __syncthreads();
    }
    if (tid < NBLK) g_bbase[tid] = (tid > 0) ? sm[tid - 1] : 0;
    if (tid == 0) g_off[NN] = NE;
}

__global__ void k_lscan() {
    __shared__ int wsum[8];
    int tid = threadIdx.x, lane = tid & 31, wid = tid >> 5;
    int base = blockIdx.x * SCAN_PER + tid * 8;

    int v[8], t = 0;
    #pragma unroll
    for (int j = 0; j < 8; j++) {
        int i = base + j;
        v[j] = (i < NN) ? g_deg_in[i] : 0;
        t += v[j];
    }
    int x = t;
    #pragma unroll
    for (int o = 1; o < 32; o <<= 1) {
        int y = __shfl_up_sync(0xffffffffu, x, o);
        if (lane >= o) x += y;
    }
    if (lane == 31) wsum[wid] = x;
    int lane_excl = x - t;
    __syncthreads();
    if (tid == 0) {
        int s = 0;
        #pragma unroll
        for (int w = 0; w < 8; w++) { int a = wsum[w]; wsum[w] = s; s += a; }
    }
    __syncthreads();
    int run = g_bbase[blockIdx.x] + wsum[wid] + lane_excl;
    #pragma unroll
    for (int j = 0; j < 8; j++) {
        int i = base + j;
        if (i < NN) { g_off[i] = run; g_cur[i] = run; }
        run += v[j];
    }
}

__global__ void k_fill(const int* __restrict__ src, const int* __restrict__ dst) {
    int e = blockIdx.x * blockDim.x + threadIdx.x;
    if (e < NE) {
        int p = atomicAdd(&g_cur[dst[e]], 1);
        g_esrc[p] = src[e];
    }
}

// layer-0 input scaling: g_A = inputs * norm_src
__global__ void k_scale0(const float* __restrict__ in) {
    int i = blockIdx.x * blockDim.x + threadIdx.x;
    if (i >= NN * DV) return;
    float s = g_ns[i / DV];
    float4 v = ((const float4*)in)[i];
    v.x *= s; v.y *= s; v.z *= s; v.w *= s;
    ((float4*)g_A)[i] = v;
}

// ---------------- aggregation ----------------
// g_T[node] = tf32( (A[node] + sum_in-edges A[src]) * norm_dst[node] )
// warp per node, float4 per lane; high occupancy (no smem) for gather MLP.

__device__ __forceinline__ unsigned f2tf32(float x) {
    unsigned u;
    asm("cvt.rna.tf32.f32 %0, %1;" : "=r"(u) : "f"(x));
    return u;
}

__global__ void k_agg() {
    int lane = threadIdx.x & 31;
    int node = (blockIdx.x * blockDim.x + threadIdx.x) >> 5;
    if (node >= NN) return;
    const float4* __restrict__ A4 = (const float4*)g_A;
    float4 a = A4[node * DV + lane];
    float ax = a.x, ay = a.y, az = a.z, aw = a.w;
    int beg = g_off[node], end = g_off[node + 1];
    for (int base = beg; base < end; base += 32) {
        int cnt = min(32, end - base);
        int e = (lane < cnt) ? __ldg(&g_esrc[base + lane]) : 0;
        #pragma unroll 4
        for (int j = 0; j < cnt; j++) {
            int s = __shfl_sync(0xffffffffu, e, j);
            float4 v = __ldg(&A4[s * DV + lane]);
            ax += v.x; ay += v.y; az += v.z; aw += v.w;
        }
    }
    float s = g_nd[node];
    ((uint4*)g_T)[node * DV + lane] =
        make_uint4(f2tf32(ax * s), f2tf32(ay * s), f2tf32(az * s), f2tf32(aw * s));
}

// ---------------- persistent tf32 GEMM ----------------
// 148 blocks x 256 threads, W resident in smem, double-buffered A tiles via
// cp.async: copy of tile t+1 overlaps mma+epilogue of tile t. No wave tail.
// out_row = A_row @ W + b ; fuse: relu(out)*norm_src -> g_A, else -> out_ext.

__global__ void __launch_bounds__(256, 1)
k_pgemm(const float* __restrict__ W, const float* __restrict__ bias,
        float* __restrict__ out_ext, int fuse) {
    extern __shared__ unsigned sm[];
    unsigned* Wsm = sm;                         // 128 x PITCH, [k][n]
    unsigned* Ab0 = sm + DIM * PITCH;           // A tile buffers
    unsigned* Ab1 = sm + 2 * DIM * PITCH;

    int tid  = threadIdx.x;
    int lane = tid & 31, w = tid >> 5;          // 8 warps
    int g = lane >> 2, t = lane & 3;
    int m0w = (w & 1) * 64;
    int n0w = (w >> 1) * 32;

    // stage W -> tf32 (plain loads; covered by first wait+sync)
    const float4* W4 = (const float4*)W;
    for (int i = tid; i < DIM * DV; i += 256) {
        int r = i >> 5, c4 = i & 31;
        float4 v = W4[i];
        *(uint4*)&Wsm[r * PITCH + c4 * 4] =
            make_uint4(f2tf32(v.x), f2tf32(v.y), f2tf32(v.z), f2tf32(v.w));
    }

    int nIter = (NT - (int)blockIdx.x + GRID_P - 1) / GRID_P;
    if (nIter <= 0) return;

    // async-stage one 128-row A tile (tf32 bits, zero past NN)
    #define STAGE(TT, AB) do {                                                   \
        int _row0 = (TT) * 128;                                                  \
        for (int i = tid; i < 128 * 32; i += 256) {                              \
            int _r = i >> 5, _c4 = i & 31;                                       \
            int _row = _row0 + _r;                                               \
            unsigned* _dp = &(AB)[_r * PITCH + _c4 * 4];                         \
            if (_row < NN) {                                                     \
                unsigned _sa = (unsigned)__cvta_generic_to_shared(_dp);          \
                const uint4* _gp = (const uint4*)&g_T[_row * DIM + _c4 * 4];     \
                asm volatile("cp.async.cg.shared.global [%0], [%1], 16;"         \
                             :: "r"(_sa), "l"(_gp));                             \
            } else {                                                             \
                *(uint4*)_dp = make_uint4(0u, 0u, 0u, 0u);                       \
            }                                                                    \
        }                                                                        \
        asm volatile("cp.async.commit_group;");                                  \
    } while (0)

    STAGE((int)blockIdx.x, Ab0);

    for (int it = 0; it < nIter; it++) {
        int tt = (int)blockIdx.x + it * GRID_P;
        unsigned* Asm = (it & 1) ? Ab1 : Ab0;

        asm volatile("cp.async.wait_group 0;");
        __syncthreads();
        if (it + 1 < nIter) {
            unsigned* nxt = (it & 1) ? Ab0 : Ab1;
            STAGE((int)blockIdx.x + (it + 1) * GRID_P, nxt);
        }

        float acc[4][4][4];
        #pragma unroll
        for (int mt = 0; mt < 4; mt++)
            #pragma unroll
            for (int nt = 0; nt < 4; nt++)
                #pragma unroll
                for (int j = 0; j < 4; j++) acc[mt][nt][j] = 0.f;

        #pragma unroll 4
        for (int k0 = 0; k0 < DIM; k0 += 8) {
            unsigned a[4][4], b[4][2];
            #pragma unroll
            for (int mt = 0; mt < 4; mt++) {
                int r = m0w + mt * 16 + g;
                a[mt][0] = Asm[r * PITCH + k0 + t];
                a[mt][1] = Asm[(r + 8) * PITCH + k0 + t];
                a[mt][2] = Asm[r * PITCH + k0 + t + 4];
                a[mt][3] = Asm[(r + 8) * PITCH + k0 + t + 4];
            }
            #pragma unroll
            for (int nt = 0; nt < 4; nt++) {
                int c = n0w + nt * 8 + g;
                b[nt][0] = Wsm[(k0 + t) * PITCH + c];
                b[nt][1] = Wsm[(k0 + t + 4) * PITCH + c];
            }
            #pragma unroll
            for (int mt = 0; mt < 4; mt++)
                #pragma unroll
                for (int nt = 0; nt < 4; nt++) {
                    asm volatile(
                        "mma.sync.aligned.m16n8k8.row.col.f32.tf32.tf32.f32 "
                        "{%0,%1,%2,%3}, {%4,%5,%6,%7}, {%8,%9}, {%0,%1,%2,%3};"
                        : "+f"(acc[mt][nt][0]), "+f"(acc[mt][nt][1]),
                          "+f"(acc[mt][nt][2]), "+f"(acc[mt][nt][3])
                        : "r"(a[mt][0]), "r"(a[mt][1]), "r"(a[mt][2]), "r"(a[mt][3]),
                          "r"(b[nt][0]), "r"(b[nt][1]));
                }
        }

        // epilogue
        int row0 = tt * 128;
        float* O = fuse ? g_A : out_ext;
        #pragma unroll
        for (int mt = 0; mt < 4; mt++) {
            int rl = row0 + m0w + mt * 16 + g;
            int rh = rl + 8;
            float sl = 1.f, sh = 1.f;
            if (fuse) {
                if (rl < NN) sl = g_ns[rl];
                if (rh < NN) sh = g_ns[rh];
            }
            #pragma unroll
            for (int nt = 0; nt < 4; nt++) {
                int c = n0w + nt * 8 + 2 * t;
                float2 bb = *(const float2*)&bias[c];
                if (rl < NN) {
                    float2 o;
                    o.x = acc[mt][nt][0] + bb.x;
                    o.y = acc[mt][nt][1] + bb.y;
                    if (fuse) { o.x = fmaxf(o.x, 0.f) * sl; o.y = fmaxf(o.y, 0.f) * sl; }
                    *(float2*)&O[rl * DIM + c] = o;
                }
                if (rh < NN) {
                    float2 o;
                    o.x = acc[mt][nt][2] + bb.x;
                    o.y = acc[mt][nt][3] + bb.y;
                    if (fuse) { o.x = fmaxf(o.x, 0.f) * sh; o.y = fmaxf(o.y, 0.f) * sh; }
                    *(float2*)&O[rh * DIM + c] = o;
                }
            }
        }
        __syncthreads();
    }
    #undef STAGE
}

// ---------------- launch ----------------

extern "C" void kernel_launch(void* const* d_in, const int* in_sizes, int n_in,
                              void* d_out, int out_size) {
    const float* inp = (const float*)d_in[0];   // [NN, DIM]
    const float* Ws  = (const float*)d_in[1];   // [3, DIM, DIM]
    const float* bs  = (const float*)d_in[2];   // [3, DIM]
    const int*   src = (const int*)  d_in[3];   // [NE]
    const int*   dst = (const int*)  d_in[4];   // [NE]
    float* out = (float*)d_out;                 // [NN, DIM]

    const int GEMM_SMEM = 3 * DIM * PITCH * (int)sizeof(unsigned);  // 208896 B
    cudaFuncSetAttribute(k_pgemm, cudaFuncAttributeMaxDynamicSharedMemorySize,
                         GEMM_SMEM);

    int nb_n = (NN + 255) / 256;
    int nb_e = (NE + 255) / 256;

    // preprocessing: degrees, norms, CSR by dst (multi-block scan)
    k_zero <<<nb_n, 256>>>();
    k_count<<<nb_e, 256>>>(src, dst);
    k_norm <<<nb_n, 256>>>();
    k_bsum <<<NBLK, 256>>>();
    k_bscan<<<1, 64>>>();
    k_lscan<<<NBLK, 256>>>();
    k_fill <<<nb_e, 256>>>(src, dst);

    // layer 0 input scaling: g_A = inputs * norm_src
    k_scale0<<<(NN * DV + 255) / 256, 256>>>(inp);

    int nb_agg = (NN * 32 + 255) / 256;   // warp per node

    for (int l = 0; l < 3; l++) {
        k_agg  <<<nb_agg, 256>>>();
        k_pgemm<<<GRID_P, 256, GEMM_SMEM>>>(Ws + l * DIM * DIM, bs + l * DIM,
                                            out, (l < 2) ? 1 : 0);
    }
}

// round 11
// speedup vs baseline: 1.8351x; 1.0760x over previous
#include <cuda_runtime.h>
#include <cuda_fp16.h>

#define NN 100000
#define NE 1600000
#define DIM 128
#define DV (DIM/4)    // 32 float4 per row
#define DH 64         // 64 half2 per row

// multi-block scan geometry: 256 threads x 8 elems = 2048 elems per block
#define SCAN_PER 2048
#define NBLK ((NN + SCAN_PER - 1) / SCAN_PER)   // 49

// smem row pitch (32-bit words): 128 + 8 pad -> W-frag loads conflict-free
#define PITCH 136
#define NT ((NN + 127) / 128)     // 782 row tiles
#define GRID_P 148                // persistent gemm grid

// ---- device scratch (allocations forbidden; globals are the sanctioned path) ----
__device__ int      g_deg_in [NN];
__device__ int      g_deg_out[NN];
__device__ float    g_ns[NN];        // rsqrt(out-degree incl self-loop)
__device__ float    g_nd[NN];        // rsqrt(in-degree  incl self-loop)
__device__ int      g_off[NN + 1];   // CSR offsets by dst
__device__ int      g_cur[NN];
__device__ int      g_esrc[NE];      // src ids bucketed by dst
__device__ int      g_bsum [NBLK];
__device__ int      g_bbase[NBLK];
__device__ __half2  g_H[NN * DH];    // fp16 feature buffer (h * norm_src) - 25.6MB
__device__ unsigned g_T[NN * DIM];   // aggregated, *norm_dst, tf32 bits

// ---------------- preprocessing ----------------

__global__ void k_zero() {
    int i = blockIdx.x * blockDim.x + threadIdx.x;
    if (i < NN) { g_deg_in[i] = 0; g_deg_out[i] = 0; }
}

__global__ void k_count(const int* __restrict__ src, const int* __restrict__ dst) {
    int e = blockIdx.x * blockDim.x + threadIdx.x;
    if (e < NE) {
        atomicAdd(&g_deg_out[src[e]], 1);
        atomicAdd(&g_deg_in [dst[e]], 1);
    }
}

__global__ void k_norm() {
    int i = blockIdx.x * blockDim.x + threadIdx.x;
    if (i < NN) {
        g_ns[i] = rsqrtf((float)(g_deg_out[i] + 1));   // +1: self-loop
        g_nd[i] = rsqrtf((float)(g_deg_in [i] + 1));
    }
}

__global__ void k_bsum() {
    __shared__ int wsum[8];
    int tid = threadIdx.x, lane = tid & 31, wid = tid >> 5;
    int base = blockIdx.x * SCAN_PER + tid * 8;
    int t = 0;
    #pragma unroll
    for (int j = 0; j < 8; j++) {
        int i = base + j;
        t += (i < NN) ? g_deg_in[i] : 0;
    }
    #pragma unroll
    for (int o = 16; o > 0; o >>= 1) t += __shfl_down_sync(0xffffffffu, t, o);
    if (lane == 0) wsum[wid] = t;
    __syncthreads();
    if (tid == 0) {
        int s = 0;
        #pragma unroll
        for (int w = 0; w < 8; w++) s += wsum[w];
        g_bsum[blockIdx.x] = s;
    }
}

__global__ void k_bscan() {
    __shared__ int sm[64];
    int tid = threadIdx.x;                       // 64 threads
    sm[tid] = (tid < NBLK) ? g_bsum[tid] : 0;
    __syncthreads();
    #pragma unroll
    for (int o = 1; o < 64; o <<= 1) {
        int v = (tid >= o) ? sm[tid - o] : 0;
        __syncthreads();
        sm[tid] += v;
        __syncthreads();
    }
    if (tid < NBLK) g_bbase[tid] = (tid > 0) ? sm[tid - 1] : 0;
    if (tid == 0) g_off[NN] = NE;
}

__global__ void k_lscan() {
    __shared__ int wsum[8];
    int tid = threadIdx.x, lane = tid & 31, wid = tid >> 5;
    int base = blockIdx.x * SCAN_PER + tid * 8;

    int v[8], t = 0;
    #pragma unroll
    for (int j = 0; j < 8; j++) {
        int i = base + j;
        v[j] = (i < NN) ? g_deg_in[i] : 0;
        t += v[j];
    }
    int x = t;
    #pragma unroll
    for (int o = 1; o < 32; o <<= 1) {
        int y = __shfl_up_sync(0xffffffffu, x, o);
        if (lane >= o) x += y;
    }
    if (lane == 31) wsum[wid] = x;
    int lane_excl = x - t;
    __syncthreads();
    if (tid == 0) {
        int s = 0;
        #pragma unroll
        for (int w = 0; w < 8; w++) { int a = wsum[w]; wsum[w] = s; s += a; }
    }
    __syncthreads();
    int run = g_bbase[blockIdx.x] + wsum[wid] + lane_excl;
    #pragma unroll
    for (int j = 0; j < 8; j++) {
        int i = base + j;
        if (i < NN) { g_off[i] = run; g_cur[i] = run; }
        run += v[j];
    }
}

__global__ void k_fill(const int* __restrict__ src, const int* __restrict__ dst) {
    int e = blockIdx.x * blockDim.x + threadIdx.x;
    if (e < NE) {
        int p = atomicAdd(&g_cur[dst[e]], 1);
        g_esrc[p] = src[e];
    }
}

// layer-0 input scaling: g_H = fp16(inputs * norm_src)
// thread handles 4 floats -> 2 half2
__global__ void k_scale0(const float* __restrict__ in) {
    int i = blockIdx.x * blockDim.x + threadIdx.x;   // float4 index
    if (i >= NN * DV) return;
    float s = g_ns[i / DV];
    float4 v = ((const float4*)in)[i];
    __half2 h0 = __floats2half2_rn(v.x * s, v.y * s);
    __half2 h1 = __floats2half2_rn(v.z * s, v.w * s);
    g_H[i * 2]     = h0;
    g_H[i * 2 + 1] = h1;
}

// ---------------- aggregation ----------------
// g_T[node] = tf32( (H[node] + sum_in-edges H[src]) * norm_dst[node] )
// warp per node; lane holds 4 feature slots (uint2 = 2x half2), fp32 accum.
// Per edge: 256 B gathered (vs 512 fp32) -> halves the L2 gather traffic.

__device__ __forceinline__ unsigned f2tf32(float x) {
    unsigned u;
    asm("cvt.rna.tf32.f32 %0, %1;" : "=r"(u) : "f"(x));
    return u;
}

__global__ void k_agg() {
    int lane = threadIdx.x & 31;
    int node = (blockIdx.x * blockDim.x + threadIdx.x) >> 5;
    if (node >= NN) return;
    const __half2* __restrict__ H = g_H;

    // self-loop
    __half2 s0 = H[node * DH + lane * 2];
    __half2 s1 = H[node * DH + lane * 2 + 1];
    float2 f0 = __half22float2(s0), f1 = __half22float2(s1);
    float ax = f0.x, ay = f0.y, az = f1.x, aw = f1.y;

    int beg = g_off[node], end = g_off[node + 1];
    for (int base = beg; base < end; base += 32) {
        int cnt = min(32, end - base);
        int e = (lane < cnt) ? __ldg(&g_esrc[base + lane]) : 0;
        #pragma unroll 4
        for (int j = 0; j < cnt; j++) {
            int s = __shfl_sync(0xffffffffu, e, j);
            // 8-byte load: 2x half2 = 4 features
            uint2 raw = __ldg((const uint2*)&H[s * DH + lane * 2]);
            __half2 h0 = *(__half2*)&raw.x;
            __half2 h1 = *(__half2*)&raw.y;
            float2 v0 = __half22float2(h0), v1 = __half22float2(h1);
            ax += v0.x; ay += v0.y; az += v1.x; aw += v1.y;
        }
    }
    float sc = g_nd[node];
    ((uint4*)g_T)[node * DV + lane] =
        make_uint4(f2tf32(ax * sc), f2tf32(ay * sc), f2tf32(az * sc), f2tf32(aw * sc));
}

// ---------------- persistent tf32 GEMM ----------------
// 148 blocks x 256 threads, W resident in smem, double-buffered A tiles via
// cp.async. out_row = A_row @ W + b ; fuse: fp16(relu(out)*norm_src) -> g_H,
// else fp32 -> out_ext.

__global__ void __launch_bounds__(256, 1)
k_pgemm(const float* __restrict__ W, const float* __restrict__ bias,
        float* __restrict__ out_ext, int fuse) {
    extern __shared__ unsigned sm[];
    unsigned* Wsm = sm;                         // 128 x PITCH, [k][n]
    unsigned* Ab0 = sm + DIM * PITCH;           // A tile buffers
    unsigned* Ab1 = sm + 2 * DIM * PITCH;

    int tid  = threadIdx.x;
    int lane = tid & 31, w = tid >> 5;          // 8 warps
    int g = lane >> 2, t = lane & 3;
    int m0w = (w & 1) * 64;
    int n0w = (w >> 1) * 32;

    // stage W -> tf32 (plain loads; covered by first wait+sync)
    const float4* W4 = (const float4*)W;
    for (int i = tid; i < DIM * DV; i += 256) {
        int r = i >> 5, c4 = i & 31;
        float4 v = W4[i];
        *(uint4*)&Wsm[r * PITCH + c4 * 4] =
            make_uint4(f2tf32(v.x), f2tf32(v.y), f2tf32(v.z), f2tf32(v.w));
    }

    int nIter = (NT - (int)blockIdx.x + GRID_P - 1) / GRID_P;
    if (nIter <= 0) return;

    #define STAGE(TT, AB) do {                                                   \
        int _row0 = (TT) * 128;                                                  \
        for (int i = tid; i < 128 * 32; i += 256) {                              \
            int _r = i >> 5, _c4 = i & 31;                                       \
            int _row = _row0 + _r;                                               \
            unsigned* _dp = &(AB)[_r * PITCH + _c4 * 4];                         \
            if (_row < NN) {                                                     \
                unsigned _sa = (unsigned)__cvta_generic_to_shared(_dp);          \
                const uint4* _gp = (const uint4*)&g_T[_row * DIM + _c4 * 4];     \
                asm volatile("cp.async.cg.shared.global [%0], [%1], 16;"         \
                             :: "r"(_sa), "l"(_gp));                             \
            } else {                                                             \
                *(uint4*)_dp = make_uint4(0u, 0u, 0u, 0u);                       \
            }                                                                    \
        }                                                                        \
        asm volatile("cp.async.commit_group;");                                  \
    } while (0)

    STAGE((int)blockIdx.x, Ab0);

    for (int it = 0; it < nIter; it++) {
        int tt = (int)blockIdx.x + it * GRID_P;
        unsigned* Asm = (it & 1) ? Ab1 : Ab0;

        asm volatile("cp.async.wait_group 0;");
        __syncthreads();
        if (it + 1 < nIter) {
            unsigned* nxt = (it & 1) ? Ab0 : Ab1;
            STAGE((int)blockIdx.x + (it + 1) * GRID_P, nxt);
        }

        float acc[4][4][4];
        #pragma unroll
        for (int mt = 0; mt < 4; mt++)
            #pragma unroll
            for (int nt = 0; nt < 4; nt++)
                #pragma unroll
                for (int j = 0; j < 4; j++) acc[mt][nt][j] = 0.f;

        #pragma unroll 4
        for (int k0 = 0; k0 < DIM; k0 += 8) {
            unsigned a[4][4], b[4][2];
            #pragma unroll
            for (int mt = 0; mt < 4; mt++) {
                int r = m0w + mt * 16 + g;
                a[mt][0] = Asm[r * PITCH + k0 + t];
                a[mt][1] = Asm[(r + 8) * PITCH + k0 + t];
                a[mt][2] = Asm[r * PITCH + k0 + t + 4];
                a[mt][3] = Asm[(r + 8) * PITCH + k0 + t + 4];
            }
            #pragma unroll
            for (int nt = 0; nt < 4; nt++) {
                int c = n0w + nt * 8 + g;
                b[nt][0] = Wsm[(k0 + t) * PITCH + c];
                b[nt][1] = Wsm[(k0 + t + 4) * PITCH + c];
            }
            #pragma unroll
            for (int mt = 0; mt < 4; mt++)
                #pragma unroll
                for (int nt = 0; nt < 4; nt++) {
                    asm volatile(
                        "mma.sync.aligned.m16n8k8.row.col.f32.tf32.tf32.f32 "
                        "{%0,%1,%2,%3}, {%4,%5,%6,%7}, {%8,%9}, {%0,%1,%2,%3};"
                        : "+f"(acc[mt][nt][0]), "+f"(acc[mt][nt][1]),
                          "+f"(acc[mt][nt][2]), "+f"(acc[mt][nt][3])
                        : "r"(a[mt][0]), "r"(a[mt][1]), "r"(a[mt][2]), "r"(a[mt][3]),
                          "r"(b[nt][0]), "r"(b[nt][1]));
                }
        }

        // epilogue
        int row0 = tt * 128;
        #pragma unroll
        for (int mt = 0; mt < 4; mt++) {
            int rl = row0 + m0w + mt * 16 + g;
            int rh = rl + 8;
            float sl = 1.f, sh = 1.f;
            if (fuse) {
                if (rl < NN) sl = g_ns[rl];
                if (rh < NN) sh = g_ns[rh];
            }
            #pragma unroll
            for (int nt = 0; nt < 4; nt++) {
                int c = n0w + nt * 8 + 2 * t;
                float2 bb = *(const float2*)&bias[c];
                if (rl < NN) {
                    float ox = acc[mt][nt][0] + bb.x;
                    float oy = acc[mt][nt][1] + bb.y;
                    if (fuse) {
                        ox = fmaxf(ox, 0.f) * sl;
                        oy = fmaxf(oy, 0.f) * sl;
                        g_H[rl * DH + (c >> 1)] = __floats2half2_rn(ox, oy);
                    } else {
                        *(float2*)&out_ext[rl * DIM + c] = make_float2(ox, oy);
                    }
                }
                if (rh < NN) {
                    float ox = acc[mt][nt][2] + bb.x;
                    float oy = acc[mt][nt][3] + bb.y;
                    if (fuse) {
                        ox = fmaxf(ox, 0.f) * sh;
                        oy = fmaxf(oy, 0.f) * sh;
                        g_H[rh * DH + (c >> 1)] = __floats2half2_rn(ox, oy);
                    } else {
                        *(float2*)&out_ext[rh * DIM + c] = make_float2(ox, oy);
                    }
                }
            }
        }
        __syncthreads();
    }
    #undef STAGE
}

// ---------------- launch ----------------

extern "C" void kernel_launch(void* const* d_in, const int* in_sizes, int n_in,
                              void* d_out, int out_size) {
    const float* inp = (const float*)d_in[0];   // [NN, DIM]
    const float* Ws  = (const float*)d_in[1];   // [3, DIM, DIM]
    const float* bs  = (const float*)d_in[2];   // [3, DIM]
    const int*   src = (const int*)  d_in[3];   // [NE]
    const int*   dst = (const int*)  d_in[4];   // [NE]
    float* out = (float*)d_out;                 // [NN, DIM]

    const int GEMM_SMEM = 3 * DIM * PITCH * (int)sizeof(unsigned);  // 208896 B
    cudaFuncSetAttribute(k_pgemm, cudaFuncAttributeMaxDynamicSharedMemorySize,
                         GEMM_SMEM);

    int nb_n = (NN + 255) / 256;
    int nb_e = (NE + 255) / 256;

    // preprocessing: degrees, norms, CSR by dst (multi-block scan)
    k_zero <<<nb_n, 256>>>();
    k_count<<<nb_e, 256>>>(src, dst);
    k_norm <<<nb_n, 256>>>();
    k_bsum <<<NBLK, 256>>>();
    k_bscan<<<1, 64>>>();
    k_lscan<<<NBLK, 256>>>();
    k_fill <<<nb_e, 256>>>(src, dst);

    // layer 0 input scaling: g_H = fp16(inputs * norm_src)
    k_scale0<<<(NN * DV + 255) / 256, 256>>>(inp);

    int nb_agg = (NN * 32 + 255) / 256;   // warp per node

    for (int l = 0; l < 3; l++) {
        k_agg  <<<nb_agg, 256>>>();
        k_pgemm<<<GRID_P, 256, GEMM_SMEM>>>(Ws + l * DIM * DIM, bs + l * DIM,
                                            out, (l < 2) ? 1 : 0);
    }
}

// round 17
// speedup vs baseline: 2.1314x; 1.1615x over previous
#include <cuda_runtime.h>
#include <cuda_fp16.h>

#define NN 100000
#define NE 1600000
#define DIM 128
#define DV (DIM/4)    // 32 float4 per row
#define DH 64         // 64 half2 per row

// multi-block scan geometry: 256 threads x 8 elems = 2048 elems per block
#define SCAN_PER 2048
#define NBLK ((NN + SCAN_PER - 1) / SCAN_PER)   // 49

// fp16 smem pitch in 32-bit words: 64 data words (128 halves) + 4 pad = 68.
// 68 % 32 == 4 -> fragment word address (r*68 + k + t) has bank (4r+k+t)%32;
// with r spanning 8 consecutive g values and t in 0..3, (4g+t) covers 0..31
// uniquely -> conflict-free a/b fragment loads. Rows stay 16B-aligned (272B).
#define PW 68
#define NT ((NN + 127) / 128)     // 782 row tiles
#define GRID_P 296                // persistent gemm grid (2 CTA/SM)

// ---- device scratch (allocations forbidden; globals are the sanctioned path) ----
__device__ int      g_deg_in [NN];
__device__ int      g_deg_out[NN];
__device__ float    g_ns[NN];        // rsqrt(out-degree incl self-loop)
__device__ float    g_nd[NN];        // rsqrt(in-degree  incl self-loop)
__device__ int      g_off[NN + 1];   // CSR offsets by dst
__device__ int      g_cur[NN];
__device__ int      g_esrc[NE];      // src ids bucketed by dst
__device__ int      g_bsum [NBLK];
__device__ int      g_bbase[NBLK];
__device__ __half2  g_H[NN * DH];    // fp16 feature buffer (h * norm_src)
__device__ __half2  g_T[NN * DH];    // aggregated * norm_dst, fp16

// ---------------- preprocessing ----------------

__global__ void k_zero() {
    int i = blockIdx.x * blockDim.x + threadIdx.x;
    if (i < NN) { g_deg_in[i] = 0; g_deg_out[i] = 0; }
}

__global__ void k_count(const int* __restrict__ src, const int* __restrict__ dst) {
    int e = blockIdx.x * blockDim.x + threadIdx.x;
    if (e < NE) {
        atomicAdd(&g_deg_out[src[e]], 1);
        atomicAdd(&g_deg_in [dst[e]], 1);
    }
}

// per-block degree sums, plus fused norm computation (saves a launch)
__global__ void k_bsum() {
    __shared__ int wsum[8];
    int tid = threadIdx.x, lane = tid & 31, wid = tid >> 5;
    int base = blockIdx.x * SCAN_PER + tid * 8;
    int t = 0;
    #pragma unroll
    for (int j = 0; j < 8; j++) {
        int i = base + j;
        if (i < NN) {
            int di = g_deg_in[i];
            t += di;
            g_nd[i] = rsqrtf((float)(di + 1));               // +1: self-loop
            g_ns[i] = rsqrtf((float)(g_deg_out[i] + 1));
        }
    }
    #pragma unroll
    for (int o = 16; o > 0; o >>= 1) t += __shfl_down_sync(0xffffffffu, t, o);
    if (lane == 0) wsum[wid] = t;
    __syncthreads();
    if (tid == 0) {
        int s = 0;
        #pragma unroll
        for (int w = 0; w < 8; w++) s += wsum[w];
        g_bsum[blockIdx.x] = s;
    }
}

__global__ void k_bscan() {
    __shared__ int sm[64];
    int tid = threadIdx.x;                       // 64 threads
    sm[tid] = (tid < NBLK) ? g_bsum[tid] : 0;
    __syncthreads();
    #pragma unroll
    for (int o = 1; o < 64; o <<= 1) {
        int v = (tid >= o) ? sm[tid - o] : 0;
        __syncthreads();
        sm[tid] += v;
        __syncthreads();
    }
    if (tid < NBLK) g_bbase[tid] = (tid > 0) ? sm[tid - 1] : 0;
    if (tid == 0) g_off[NN] = NE;
}

__global__ void k_lscan() {
    __shared__ int wsum[8];
    int tid = threadIdx.x, lane = tid & 31, wid = tid >> 5;
    int base = blockIdx.x * SCAN_PER + tid * 8;

    int v[8], t = 0;
    #pragma unroll
    for (int j = 0; j < 8; j++) {
        int i = base + j;
        v[j] = (i < NN) ? g_deg_in[i] : 0;
        t += v[j];
    }
    int x = t;
    #pragma unroll
    for (int o = 1; o < 32; o <<= 1) {
        int y = __shfl_up_sync(0xffffffffu, x, o);
        if (lane >= o) x += y;
    }
    if (lane == 31) wsum[wid] = x;
    int lane_excl = x - t;
    __syncthreads();
    if (tid == 0) {
        int s = 0;
        #pragma unroll
        for (int w = 0; w < 8; w++) { int a = wsum[w]; wsum[w] = s; s += a; }
    }
    __syncthreads();
    int run = g_bbase[blockIdx.x] + wsum[wid] + lane_excl;
    #pragma unroll
    for (int j = 0; j < 8; j++) {
        int i = base + j;
        if (i < NN) { g_off[i] = run; g_cur[i] = run; }
        run += v[j];
    }
}

__global__ void k_fill(const int* __restrict__ src, const int* __restrict__ dst) {
    int e = blockIdx.x * blockDim.x + threadIdx.x;
    if (e < NE) {
        int p = atomicAdd(&g_cur[dst[e]], 1);
        g_esrc[p] = src[e];
    }
}

// layer-0 input scaling: g_H = fp16(inputs * norm_src)
__global__ void k_scale0(const float* __restrict__ in) {
    int i = blockIdx.x * blockDim.x + threadIdx.x;   // float4 index
    if (i >= NN * DV) return;
    float s = g_ns[i / DV];
    float4 v = ((const float4*)in)[i];
    g_H[i * 2]     = __floats2half2_rn(v.x * s, v.y * s);
    g_H[i * 2 + 1] = __floats2half2_rn(v.z * s, v.w * s);
}

// ---------------- aggregation ----------------
// g_T[node] = fp16( (H[node] + sum_in-edges H[src]) * norm_dst[node] )
// warp per node; TWO edges in flight per iteration: half-warp h processes
// edge j+h, 16 lanes x uint4 (16B) cover the 256B row. fp32 accumulation;
// cross-half reduce via shfl_xor(16) at the end.

__device__ __forceinline__ void acc8(float* a, uint4 r) {
    float2 f;
    f = __half22float2(*(__half2*)&r.x); a[0] += f.x; a[1] += f.y;
    f = __half22float2(*(__half2*)&r.y); a[2] += f.x; a[3] += f.y;
    f = __half22float2(*(__half2*)&r.z); a[4] += f.x; a[5] += f.y;
    f = __half22float2(*(__half2*)&r.w); a[6] += f.x; a[7] += f.y;
}

__global__ void k_agg() {
    int lane = threadIdx.x & 31;
    int node = (blockIdx.x * blockDim.x + threadIdx.x) >> 5;
    if (node >= NN) return;
    int h = lane >> 4;          // half-warp id (which edge of the pair)
    int c = lane & 15;          // uint4 column within the 256B row
    const uint4* __restrict__ H4 = (const uint4*)g_H;   // 16 uint4 per row

    float acc[8];
    #pragma unroll
    for (int i = 0; i < 8; i++) acc[i] = 0.f;

    if (h == 0) {               // self-loop counted once
        uint4 sv = __ldg(&H4[node * 16 + c]);
        acc8(acc, sv);
    }

    int beg = g_off[node], end = g_off[node + 1];
    for (int base = beg; base < end; base += 32) {
        int cnt = min(32, end - base);
        int e = (lane < cnt) ? __ldg(&g_esrc[base + lane]) : 0;
        #pragma unroll 4
        for (int j = 0; j < cnt; j += 2) {
            int jj = j + h;
            int s = __shfl_sync(0xffffffffu, e, jj & 31);
            if (jj < cnt) {
                uint4 v = __ldg(&H4[s * 16 + c]);
                acc8(acc, v);
            }
        }
    }

    #pragma unroll
    for (int i = 0; i < 8; i++)
        acc[i] += __shfl_xor_sync(0xffffffffu, acc[i], 16);

    if (h == 0) {
        float sc = g_nd[node];
        __half2 p0 = __floats2half2_rn(acc[0] * sc, acc[1] * sc);
        __half2 p1 = __floats2half2_rn(acc[2] * sc, acc[3] * sc);
        __half2 p2 = __floats2half2_rn(acc[4] * sc, acc[5] * sc);
        __half2 p3 = __floats2half2_rn(acc[6] * sc, acc[7] * sc);
        uint4 o;
        o.x = *(unsigned*)&p0; o.y = *(unsigned*)&p1;
        o.z = *(unsigned*)&p2; o.w = *(unsigned*)&p3;
        ((uint4*)g_T)[node * 16 + c] = o;
    }
}

// ---------------- persistent fp16 GEMM ----------------
// 296 blocks x 256 threads (2 CTA/SM), W^T resident in smem as fp16,
// double-buffered fp16 A tiles via cp.async. mma.m16n8k16.f16 (fp32 accum).
// out_row = A_row @ W + b ; fuse: fp16(relu(out)*norm_src) -> g_H,
// else fp32 -> out_ext.

__global__ void __launch_bounds__(256, 2)
k_pgemm(const float* __restrict__ W, const float* __restrict__ bias,
        float* __restrict__ out_ext, int fuse) {
    extern __shared__ unsigned sm[];
    unsigned* Wsm = sm;                  // W^T: [n][k], 128 rows x PW words
    unsigned* Ab0 = sm + DIM * PW;       // A tiles: [m][k], 128 rows x PW words
    unsigned* Ab1 = sm + 2 * DIM * PW;

    int tid  = threadIdx.x;
    int lane = tid & 31, w = tid >> 5;   // 8 warps
    int g = lane >> 2, t = lane & 3;
    int m0w = (w & 1) * 64;
    int n0w = (w >> 1) * 32;

    // stage W^T -> fp16 smem: read W[k][n] coalesced, scatter halves to [n][k]
    __half* Wh = (__half*)Wsm;           // pitch PW*2 = 136 halves per n-row
    const float4* W4 = (const float4*)W;
    for (int i = tid; i < DIM * DV; i += 256) {
        int k = i >> 5, n4 = (i & 31) * 4;
        float4 v = W4[i];
        Wh[(n4 + 0) * (PW * 2) + k] = __float2half_rn(v.x);
        Wh[(n4 + 1) * (PW * 2) + k] = __float2half_rn(v.y);
        Wh[(n4 + 2) * (PW * 2) + k] = __float2half_rn(v.z);
        Wh[(n4 + 3) * (PW * 2) + k] = __float2half_rn(v.w);
    }

    int nIter = (NT - (int)blockIdx.x + GRID_P - 1) / GRID_P;
    if (nIter <= 0) return;

    // async-stage one 128-row fp16 A tile (rows are 256B = 16 x 16B chunks;
    // chunk _c covers half2 indices 4*_c .. 4*_c+3 -> g_T offset _c * 4)
    #define STAGE(TT, AB) do {                                                   \
        int _row0 = (TT) * 128;                                                  \
        for (int i = tid; i < 128 * 16; i += 256) {                              \
            int _r = i >> 4, _c = i & 15;                                        \
            int _row = _row0 + _r;                                               \
            unsigned* _dp = &(AB)[_r * PW + _c * 4];                             \
            if (_row < NN) {                                                     \
                unsigned _sa = (unsigned)__cvta_generic_to_shared(_dp);          \
                const uint4* _gp = (const uint4*)&g_T[_row * DH + _c * 4];       \
                asm volatile("cp.async.cg.shared.global [%0], [%1], 16;"         \
                             :: "r"(_sa), "l"(_gp));                             \
            } else {                                                             \
                *(uint4*)_dp = make_uint4(0u, 0u, 0u, 0u);                       \
            }                                                                    \
        }                                                                        \
        asm volatile("cp.async.commit_group;");                                  \
    } while (0)

    STAGE((int)blockIdx.x, Ab0);

    for (int it = 0; it < nIter; it++) {
        int tt = (int)blockIdx.x + it * GRID_P;
        unsigned* Asm = (it & 1) ? Ab1 : Ab0;

        asm volatile("cp.async.wait_group 0;");
        __syncthreads();
        if (it + 1 < nIter) {
            unsigned* nxt = (it & 1) ? Ab0 : Ab1;
            STAGE((int)blockIdx.x + (it + 1) * GRID_P, nxt);
        }

        float acc[4][4][4];
        #pragma unroll
        for (int mt = 0; mt < 4; mt++)
            #pragma unroll
            for (int nt = 0; nt < 4; nt++)
                #pragma unroll
                for (int j = 0; j < 4; j++) acc[mt][nt][j] = 0.f;

        #pragma unroll
        for (int kh = 0; kh < DIM / 2; kh += 8) {       // k-block of 16 halves
            unsigned a[4][4], b[4][2];
            #pragma unroll
            for (int mt = 0; mt < 4; mt++) {
                int r = m0w + mt * 16 + g;
                a[mt][0] = Asm[r * PW + kh + t];
                a[mt][1] = Asm[(r + 8) * PW + kh + t];
                a[mt][2] = Asm[r * PW + kh + t + 4];
                a[mt][3] = Asm[(r + 8) * PW + kh + t + 4];
            }
            #pragma unroll
            for (int nt = 0; nt < 4; nt++) {
                int cn = n0w + nt * 8 + g;
                b[nt][0] = Wsm[cn * PW + kh + t];
                b[nt][1] = Wsm[cn * PW + kh + t + 4];
            }
            #pragma unroll
            for (int mt = 0; mt < 4; mt++)
                #pragma unroll
                for (int nt = 0; nt < 4; nt++) {
                    asm volatile(
                        "mma.sync.aligned.m16n8k16.row.col.f32.f16.f16.f32 "
                        "{%0,%1,%2,%3}, {%4,%5,%6,%7}, {%8,%9}, {%0,%1,%2,%3};"
                        : "+f"(acc[mt][nt][0]), "+f"(acc[mt][nt][1]),
                          "+f"(acc[mt][nt][2]), "+f"(acc[mt][nt][3])
                        : "r"(a[mt][0]), "r"(a[mt][1]), "r"(a[mt][2]), "r"(a[mt][3]),
                          "r"(b[nt][0]), "r"(b[nt][1]));
                }
        }

        // epilogue
        int row0 = tt * 128;
        #pragma unroll
        for (int mt = 0; mt < 4; mt++) {
            int rl = row0 + m0w + mt * 16 + g;
            int rh = rl + 8;
            float sl = 1.f, sh = 1.f;
            if (fuse) {
                if (rl < NN) sl = g_ns[rl];
                if (rh < NN) sh = g_ns[rh];
            }
            #pragma unroll
            for (int nt = 0; nt < 4; nt++) {
                int cc = n0w + nt * 8 + 2 * t;
                float2 bb = *(const float2*)&bias[cc];
                if (rl < NN) {
                    float ox = acc[mt][nt][0] + bb.x;
                    float oy = acc[mt][nt][1] + bb.y;
                    if (fuse) {
                        ox = fmaxf(ox, 0.f) * sl;
                        oy = fmaxf(oy, 0.f) * sl;
                        g_H[rl * DH + (cc >> 1)] = __floats2half2_rn(ox, oy);
                    } else {
                        *(float2*)&out_ext[rl * DIM + cc] = make_float2(ox, oy);
                    }
                }
                if (rh < NN) {
                    float ox = acc[mt][nt][2] + bb.x;
                    float oy = acc[mt][nt][3] + bb.y;
                    if (fuse) {
                        ox = fmaxf(ox, 0.f) * sh;
                        oy = fmaxf(oy, 0.f) * sh;
                        g_H[rh * DH + (cc >> 1)] = __floats2half2_rn(ox, oy);
                    } else {
                        *(float2*)&out_ext[rh * DIM + cc] = make_float2(ox, oy);
                    }
                }
            }
        }
        __syncthreads();
    }
    #undef STAGE
}

// ---------------- launch ----------------

extern "C" void kernel_launch(void* const* d_in, const int* in_sizes, int n_in,
                              void* d_out, int out_size) {
    const float* inp = (const float*)d_in[0];   // [NN, DIM]
    const float* Ws  = (const float*)d_in[1];   // [3, DIM, DIM]
    const float* bs  = (const float*)d_in[2];   // [3, DIM]
    const int*   src = (const int*)  d_in[3];   // [NE]
    const int*   dst = (const int*)  d_in[4];   // [NE]
    float* out = (float*)d_out;                 // [NN, DIM]

    const int GEMM_SMEM = 3 * DIM * PW * (int)sizeof(unsigned);  // 104448 B
    cudaFuncSetAttribute(k_pgemm, cudaFuncAttributeMaxDynamicSharedMemorySize,
                         GEMM_SMEM);

    int nb_n = (NN + 255) / 256;
    int nb_e = (NE + 255) / 256;

    // preprocessing: degrees, norms (fused into bsum), CSR by dst
    k_zero <<<nb_n, 256>>>();
    k_count<<<nb_e, 256>>>(src, dst);
    k_bsum <<<NBLK, 256>>>();
    k_bscan<<<1, 64>>>();
    k_lscan<<<NBLK, 256>>>();
    k_fill <<<nb_e, 256>>>(src, dst);

    // layer 0 input scaling: g_H = fp16(inputs * norm_src)
    k_scale0<<<(NN * DV + 255) / 256, 256>>>(inp);

    int nb_agg = (NN * 32 + 255) / 256;   // warp per node

    for (int l = 0; l < 3; l++) {
        k_agg  <<<nb_agg, 256>>>();
        k_pgemm<<<GRID_P, 256, GEMM_SMEM>>>(Ws + l * DIM * DIM, bs + l * DIM,
                                            out, (l < 2) ? 1 : 0);
    }
}